// round 9
// baseline (speedup 1.0000x reference)
#include <cuda_runtime.h>
#include <math.h>

// ---------------- problem constants ----------------
#define BATCH 512
#define TIN   512
#define CCH   6
#define HID   12
#define NLAY  120
#define T1    508        // after conv1 (k=5 VALID)
#define T2    504        // after conv2
#define GL    20         // layers per pipeline group
#define NGRP  6          // 120 / 20
#define NTH   240        // GL * HID threads in LSTM block
#define NQUAD 128        // batch quads (4 per block)
#define NOUT  (BATCH*NLAY*HID)   // 737280 per output tensor

typedef unsigned long long u64;

// dynamic smem for k_lstm:
//   seq  : T2*HID ulonglong2 (4 batches packed as 2 x f32x2)   = 96768 B
//   hbuf : 2*GL*HID ulonglong2 (h ring, 4 batches)             =  7680 B
//   bias : NTH*4 u64 (packed gate biases per thread)           =  7680 B
#define SEQ_U2   (T2*HID)
#define HBUF_U2  (2*GL*HID)
#define BIAS_U64 (NTH*4)
#define LSTM_SMEM_BYTES (SEQ_U2*16 + HBUF_U2*16 + BIAS_U64*8)

// ---------------- device scratch (static, no allocation) ----------------
__device__ double g_s1[CCH], g_q1[CCH], g_s2[CCH], g_q2[CCH];
__device__ float  g_bn1[2*CCH];   // scale[6], shift[6]
__device__ float  g_bn2[2*CCH];
__device__ float  g_buf1[BATCH*CCH*T1];
__device__ float  g_buf2[BATCH*CCH*T2];
__device__ float  g_seq [BATCH*T2*HID];   // quad-interleaved: [quad][t][h][lane4]
__device__ float  g_hid [BATCH*NLAY*HID];

// ---------------- f32x2 helpers (b64 operands -> "l" constraint) ----------------
__device__ __forceinline__ u64 ffma2(u64 a, u64 b, u64 c) {
    u64 d;
    asm("fma.rn.f32x2 %0, %1, %2, %3;" : "=l"(d) : "l"(a), "l"(b), "l"(c));
    return d;
}
__device__ __forceinline__ u64 pack2(float x, float y) {
    u64 d;
    asm("mov.b64 %0, {%1, %2};" : "=l"(d) : "f"(x), "f"(y));
    return d;
}
__device__ __forceinline__ void unpack2(u64 d, float& x, float& y) {
    asm("mov.b64 {%0, %1}, %2;" : "=f"(x), "=f"(y) : "l"(d));
}

// ---------------- activation helpers ----------------
__device__ __forceinline__ float tanh_t(float x) {
    float y;
    asm("tanh.approx.f32 %0, %1;" : "=f"(y) : "f"(x));
    return y;
}
__device__ __forceinline__ float sigm_t(float x) {
    return fmaf(0.5f, tanh_t(0.5f * x), 0.5f);
}

// ---------------- K0: zero BN stat accumulators ----------------
__global__ void k_zero() {
    int t = threadIdx.x;
    if (t < CCH) { g_s1[t] = 0.0; g_q1[t] = 0.0; g_s2[t] = 0.0; g_q2[t] = 0.0; }
}

// ---------------- K1: conv1 + BN1 stats ----------------
__global__ void k_conv1(const float* __restrict__ x,
                        const float* __restrict__ w,
                        const float* __restrict__ bias) {
    int b = blockIdx.x;
    int tid = threadIdx.x;
    __shared__ float xs[CCH * TIN];
    __shared__ float ws[CCH * CCH * 5];
    __shared__ float bs[CCH];
    for (int i = tid; i < CCH * TIN; i += blockDim.x) xs[i] = x[b * CCH * TIN + i];
    if (tid < CCH * CCH * 5) ws[tid] = w[tid];
    if (tid < CCH) bs[tid] = bias[tid];
    __syncthreads();

    for (int c = 0; c < CCH; c++) {
        float s = 0.f, q = 0.f;
        for (int t = tid; t < T1; t += blockDim.x) {
            float a = bs[c];
            #pragma unroll
            for (int ci = 0; ci < CCH; ci++) {
                const float* xp = xs + ci * TIN + t;
                const float* wp = ws + (c * CCH + ci) * 5;
                #pragma unroll
                for (int k = 0; k < 5; k++) a = fmaf(xp[k], wp[k], a);
            }
            g_buf1[(b * CCH + c) * T1 + t] = a;
            s += a; q += a * a;
        }
        #pragma unroll
        for (int off = 16; off > 0; off >>= 1) {
            s += __shfl_down_sync(0xffffffffu, s, off);
            q += __shfl_down_sync(0xffffffffu, q, off);
        }
        if ((tid & 31) == 0) {
            atomicAdd(&g_s1[c], (double)s);
            atomicAdd(&g_q1[c], (double)q);
        }
    }
}

// ---------------- K2/K4: finalize BN scale/shift ----------------
__global__ void k_bnfin(const float* __restrict__ gam,
                        const float* __restrict__ bet, int which) {
    int c = threadIdx.x;
    if (c < CCH) {
        double* S = which ? g_s2 : g_s1;
        double* Q = which ? g_q2 : g_q1;
        float* out = which ? g_bn2 : g_bn1;
        double n = which ? ((double)BATCH * T2) : ((double)BATCH * T1);
        double m = S[c] / n;
        double v = Q[c] / n - m * m;
        float sc = gam[c] * rsqrtf((float)v + 1e-5f);
        out[c] = sc;
        out[CCH + c] = bet[c] - (float)m * sc;
    }
}

// ---------------- K3: BN1+relu -> conv2 + BN2 stats ----------------
__global__ void k_conv2(const float* __restrict__ w,
                        const float* __restrict__ bias) {
    int b = blockIdx.x;
    int tid = threadIdx.x;
    __shared__ float xs[CCH * T1];
    __shared__ float ws[CCH * CCH * 5];
    __shared__ float bs[CCH];
    for (int i = tid; i < CCH * T1; i += blockDim.x) {
        int ci = i / T1;
        float v = g_buf1[b * CCH * T1 + i];
        xs[i] = fmaxf(fmaf(v, g_bn1[ci], g_bn1[CCH + ci]), 0.f);
    }
    if (tid < CCH * CCH * 5) ws[tid] = w[tid];
    if (tid < CCH) bs[tid] = bias[tid];
    __syncthreads();

    for (int c = 0; c < CCH; c++) {
        float s = 0.f, q = 0.f;
        for (int t = tid; t < T2; t += blockDim.x) {
            float a = bs[c];
            #pragma unroll
            for (int ci = 0; ci < CCH; ci++) {
                const float* xp = xs + ci * T1 + t;
                const float* wp = ws + (c * CCH + ci) * 5;
                #pragma unroll
                for (int k = 0; k < 5; k++) a = fmaf(xp[k], wp[k], a);
            }
            g_buf2[(b * CCH + c) * T2 + t] = a;
            s += a; q += a * a;
        }
        #pragma unroll
        for (int off = 16; off > 0; off >>= 1) {
            s += __shfl_down_sync(0xffffffffu, s, off);
            q += __shfl_down_sync(0xffffffffu, q, off);
        }
        if ((tid & 31) == 0) {
            atomicAdd(&g_s2[c], (double)s);
            atomicAdd(&g_q2[c], (double)q);
        }
    }
}

// ---------------- K5: BN2+relu -> attn -> seq (batch-quad interleaved) ----------------
__global__ void k_attn(const float* __restrict__ aw,
                       const float* __restrict__ ab) {
    int b = blockIdx.x;
    int tid = threadIdx.x;
    __shared__ float xs[CCH * T2];
    __shared__ float ws[HID * CCH];
    __shared__ float bs[HID];
    for (int i = tid; i < CCH * T2; i += blockDim.x) {
        int ci = i / T2;
        float v = g_buf2[b * CCH * T2 + i];
        xs[i] = fmaxf(fmaf(v, g_bn2[ci], g_bn2[CCH + ci]), 0.f);
    }
    if (tid < HID * CCH) ws[tid] = aw[tid];
    if (tid < HID) bs[tid] = ab[tid];
    __syncthreads();

    size_t base = ((size_t)(b >> 2)) * T2 * HID * 4 + (b & 3);
    for (int idx = tid; idx < T2 * HID; idx += blockDim.x) {
        int t = idx / HID, h = idx % HID;
        float a = bs[h];
        #pragma unroll
        for (int c = 0; c < CCH; c++) a = fmaf(xs[c * T2 + t], ws[h * CCH + c], a);
        g_seq[base + (size_t)idx * 4] = fmaxf(a, 0.f);
    }
}

// ---------------- K6: 120-layer LSTM, 4 batches/block via dual f32x2 streams ----------------
// Warps 0-3 process pair A (lanes .x) then pair B (.y); warps 4-7 the reverse.
// SMSP co-resident warps are {w, w+4}, so each SMSP gets one warp of each
// phase: while one warp runs its MUFU/activation section, the other issues
// FFMA2 -- un-serializing the per-tick pipe phases.
//
// PROC_PAIR(OFF, CA, CB, HA, HB): gate math for the batch pair at u64 lane
// offset OFF (0 = .x, 1 = .y); updates cell regs CA,CB and writes HA,HB.
#define PROC_PAIR(OFF, CA, CB, HA, HB)                                        \
    {                                                                         \
        u64 a0 = bz0, a1 = bz1, a2 = bz2v, a3 = bz3;                          \
        _Pragma("unroll")                                                     \
        for (int m = 0; m < HID; m++) {                                       \
            u64 xm = xq[2 * m + (OFF)];                                       \
            a0 = ffma2(wih2[0][m], xm, a0);                                   \
            a1 = ffma2(wih2[1][m], xm, a1);                                   \
            a2 = ffma2(wih2[2][m], xm, a2);                                   \
            a3 = ffma2(wih2[3][m], xm, a3);                                   \
        }                                                                     \
        _Pragma("unroll")                                                     \
        for (int m = 0; m < HID; m++) {                                       \
            u64 hm = hq[2 * m + (OFF)];                                       \
            a0 = ffma2(whh2[0][m], hm, a0);                                   \
            a1 = ffma2(whh2[1][m], hm, a1);                                   \
            a2 = ffma2(whh2[2][m], hm, a2);                                   \
            a3 = ffma2(whh2[3][m], hm, a3);                                   \
        }                                                                     \
        float gi0, gi1, gf0, gf1, gg0, gg1, go0, go1;                         \
        unpack2(a0, gi0, gi1);                                                \
        unpack2(a1, gf0, gf1);                                                \
        unpack2(a2, gg0, gg1);                                                \
        unpack2(a3, go0, go1);                                                \
        float gi = sigm_t(gi0), gf = sigm_t(gf0);                             \
        float gg = tanh_t(gg0), go = sigm_t(go0);                             \
        CA = gf * CA + gi * gg;                                               \
        HA = go * tanh_t(CA);                                                 \
        gi = sigm_t(gi1); gf = sigm_t(gf1);                                   \
        gg = tanh_t(gg1); go = sigm_t(go1);                                   \
        CB = gf * CB + gi * gg;                                               \
        HB = go * tanh_t(CB);                                                 \
    }

__global__ void __launch_bounds__(NTH, 1)
k_lstm(const float* __restrict__ Wih, const float* __restrict__ Whh,
       const float* __restrict__ bih, const float* __restrict__ bhh) {
    extern __shared__ __align__(16) char smraw[];
    ulonglong2* seq_s = (ulonglong2*)smraw;                    // [T2*HID]
    ulonglong2* hbuf  = (ulonglong2*)(smraw + SEQ_U2 * 16);    // [2][GL][HID]
    u64*        bias_s= (u64*)(smraw + SEQ_U2 * 16 + HBUF_U2 * 16); // [NTH][4]

    int quad = blockIdx.x;
    int b0 = quad * 4;
    int tid = threadIdx.x;
    int j = tid / HID;   // local layer in group
    int i = tid % HID;   // hidden unit
    bool firstB = ((tid >> 7) & 1) != 0;   // warps 4-7: pair B first

    // load this quad's interleaved sequence into shared (96 KB)
    {
        const ulonglong2* src = (const ulonglong2*)(g_seq + (size_t)quad * T2 * HID * 4);
        for (int q = tid; q < SEQ_U2; q += NTH) seq_s[q] = src[q];
    }

    for (int grp = 0; grp < NGRP; grp++) {
        int l = grp * GL + j;
        // zero h ring (h0 = c0 = 0)
        for (int q = tid; q < HBUF_U2; q += NTH)
            hbuf[q] = make_ulonglong2(0ull, 0ull);

        // pack this thread's 4 gate rows into duplicated-lane f32x2 registers
        u64 wih2[4][HID], whh2[4][HID];
        {
            const float* Wi = Wih + (size_t)l * 48 * HID;
            const float* Wh = Whh + (size_t)l * 48 * HID;
            #pragma unroll
            for (int r = 0; r < 4; r++) {
                int row = r * HID + i;
                #pragma unroll
                for (int m = 0; m < HID; m++) {
                    float wi = Wi[row * HID + m];
                    float wh = Wh[row * HID + m];
                    wih2[r][m] = pack2(wi, wi);
                    whh2[r][m] = pack2(wh, wh);
                }
                float bb = bih[l * 48 + row] + bhh[l * 48 + row];
                bias_s[tid * 4 + r] = pack2(bb, bb);
            }
        }
        float c0 = 0.f, c1 = 0.f, c2 = 0.f, c3 = 0.f;
        __syncthreads();

        for (int k = 0; k < T2 + GL - 1; k++) {
            int t = k - j;
            if ((unsigned)t < (unsigned)T2) {
                int p = k & 1;
                const ulonglong2* xp2 = (j == 0) ? (seq_s + t * HID)
                                                 : (hbuf + ((p ^ 1) * GL + (j - 1)) * HID);
                const ulonglong2* hp2 = hbuf + ((p ^ 1) * GL + j) * HID;
                const u64* xq = (const u64*)xp2;
                const u64* hq = (const u64*)hp2;

                u64 bz0 = bias_s[tid * 4 + 0], bz1 = bias_s[tid * 4 + 1];
                u64 bz2v = bias_s[tid * 4 + 2], bz3 = bias_s[tid * 4 + 3];

                float h0, h1, h2, h3;
                if (firstB) {
                    PROC_PAIR(1, c2, c3, h2, h3);
                    PROC_PAIR(0, c0, c1, h0, h1);
                } else {
                    PROC_PAIR(0, c0, c1, h0, h1);
                    PROC_PAIR(1, c2, c3, h2, h3);
                }

                ulonglong2 hvq = make_ulonglong2(pack2(h0, h1), pack2(h2, h3));
                hbuf[(p * GL + j) * HID + i] = hvq;
                if (j == GL - 1) seq_s[t * HID + i] = hvq;  // feeds next group
                if (t == T2 - 1) {
                    g_hid[((size_t)(b0 + 0) * NLAY + l) * HID + i] = h0;
                    g_hid[((size_t)(b0 + 1) * NLAY + l) * HID + i] = h1;
                    g_hid[((size_t)(b0 + 2) * NLAY + l) * HID + i] = h2;
                    g_hid[((size_t)(b0 + 3) * NLAY + l) * HID + i] = h3;
                }
            }
            __syncthreads();
        }
        __syncthreads();
    }
}
#undef PROC_PAIR

// ---------------- K7: MLP head -> (z, out, mu, log_var) ----------------
__global__ void k_head(const float* __restrict__ eps,
                       const float* __restrict__ l1w, const float* __restrict__ l1b,
                       const float* __restrict__ l2w, const float* __restrict__ l2b,
                       const float* __restrict__ muw, const float* __restrict__ mub,
                       const float* __restrict__ lvw, const float* __restrict__ lvb,
                       float* __restrict__ out) {
    __shared__ float W1[144], W2[144], WM[144], WV[144];
    __shared__ float B1[12], B2[12], BM[12], BV[12];
    int tid = threadIdx.x;
    for (int q = tid; q < 144; q += blockDim.x) {
        W1[q] = l1w[q]; W2[q] = l2w[q]; WM[q] = muw[q]; WV[q] = lvw[q];
    }
    if (tid < 12) { B1[tid] = l1b[tid]; B2[tid] = l2b[tid]; BM[tid] = mub[tid]; BV[tid] = lvb[tid]; }
    __syncthreads();

    int row = blockIdx.x * blockDim.x + tid;       // (b*120 + l)
    if (row >= BATCH * NLAY) return;
    const float* hp = g_hid + (size_t)row * HID;
    float h[HID], v1[HID], v2[HID];
    {
        float4 a = *(const float4*)(hp);
        float4 bq = *(const float4*)(hp + 4);
        float4 cq = *(const float4*)(hp + 8);
        h[0]=a.x; h[1]=a.y; h[2]=a.z; h[3]=a.w; h[4]=bq.x; h[5]=bq.y; h[6]=bq.z; h[7]=bq.w;
        h[8]=cq.x; h[9]=cq.y; h[10]=cq.z; h[11]=cq.w;
    }
    #pragma unroll
    for (int r = 0; r < HID; r++) {
        float a = B1[r];
        #pragma unroll
        for (int m = 0; m < HID; m++) a = fmaf(W1[r * HID + m], h[m], a);
        v1[r] = fmaxf(a, 0.f);
    }
    #pragma unroll
    for (int r = 0; r < HID; r++) {
        float a = B2[r];
        #pragma unroll
        for (int m = 0; m < HID; m++) a = fmaf(W2[r * HID + m], v1[m], a);
        v2[r] = fmaxf(a, 0.f);
    }
    #pragma unroll
    for (int r = 0; r < HID; r++) {
        float mu = BM[r], lv = BV[r];
        #pragma unroll
        for (int m = 0; m < HID; m++) {
            mu = fmaf(WM[r * HID + m], v2[m], mu);
            lv = fmaf(WV[r * HID + m], v2[m], lv);
        }
        float e = eps[(size_t)row * HID + r];
        float z = fmaf(__expf(0.5f * lv), e, mu);
        size_t idx = (size_t)row * HID + r;
        out[idx]              = z;
        out[NOUT + idx]       = v2[r];
        out[2 * (size_t)NOUT + idx] = mu;
        out[3 * (size_t)NOUT + idx] = lv;
    }
}

// ---------------- launcher ----------------
extern "C" void kernel_launch(void* const* d_in, const int* in_sizes, int n_in,
                              void* d_out, int out_size) {
    const float* x    = (const float*)d_in[0];
    const float* eps  = (const float*)d_in[1];
    const float* c1w  = (const float*)d_in[2];
    const float* c1b  = (const float*)d_in[3];
    const float* c2w  = (const float*)d_in[4];
    const float* c2b  = (const float*)d_in[5];
    const float* bn1g = (const float*)d_in[6];
    const float* bn1b = (const float*)d_in[7];
    const float* bn2g = (const float*)d_in[8];
    const float* bn2b = (const float*)d_in[9];
    const float* aw   = (const float*)d_in[10];
    const float* ab   = (const float*)d_in[11];
    const float* Wih  = (const float*)d_in[12];
    const float* Whh  = (const float*)d_in[13];
    const float* bih  = (const float*)d_in[14];
    const float* bhh  = (const float*)d_in[15];
    const float* l1w  = (const float*)d_in[16];
    const float* l1b  = (const float*)d_in[17];
    const float* l2w  = (const float*)d_in[18];
    const float* l2b  = (const float*)d_in[19];
    const float* muw  = (const float*)d_in[20];
    const float* mub  = (const float*)d_in[21];
    const float* lvw  = (const float*)d_in[22];
    const float* lvb  = (const float*)d_in[23];

    cudaFuncSetAttribute(k_lstm, cudaFuncAttributeMaxDynamicSharedMemorySize,
                         LSTM_SMEM_BYTES);

    k_zero<<<1, 32>>>();
    k_conv1<<<BATCH, 256>>>(x, c1w, c1b);
    k_bnfin<<<1, 32>>>(bn1g, bn1b, 0);
    k_conv2<<<BATCH, 256>>>(c2w, c2b);
    k_bnfin<<<1, 32>>>(bn2g, bn2b, 1);
    k_attn<<<BATCH, 256>>>(aw, ab);
    k_lstm<<<NQUAD, NTH, LSTM_SMEM_BYTES>>>(Wih, Whh, bih, bhh);
    k_head<<<(BATCH * NLAY) / 128, 128>>>(eps, l1w, l1b, l2w, l2b, muw, mub, lvw, lvb,
                                          (float*)d_out);
}

// round 10
// speedup vs baseline: 1.0757x; 1.0757x over previous
#include <cuda_runtime.h>
#include <math.h>

// ---------------- problem constants ----------------
#define BATCH 512
#define TIN   512
#define CCH   6
#define HID   12
#define NLAY  120
#define T1    508        // after conv1 (k=5 VALID)
#define T2    504        // after conv2
#define GL    10         // layers per pipeline group
#define NGRP  12         // 120 / 10
#define NTH   120        // GL * HID threads in LSTM block
#define NPAIR 256        // batch pairs (2 per block)
#define NOUT  (BATCH*NLAY*HID)   // 737280 per output tensor

typedef unsigned long long u64;

// dynamic smem for k_lstm (all u64):
//   seq  : T2*HID     packed (b0,b1)      = 48384 B
//   hbuf : 2*GL*HID   h ring              =  1920 B
//   bias : NTH*4      packed gate biases  =  3840 B
#define SEQ_U   (T2*HID)
#define HBUF_U  (2*GL*HID)
#define BIAS_U  (NTH*4)
#define LSTM_SMEM_BYTES ((SEQ_U + HBUF_U + BIAS_U) * 8)

// ---------------- device scratch (static, no allocation) ----------------
__device__ double g_s1[CCH], g_q1[CCH], g_s2[CCH], g_q2[CCH];
__device__ float  g_bn1[2*CCH];   // scale[6], shift[6]
__device__ float  g_bn2[2*CCH];
__device__ float  g_buf1[BATCH*CCH*T1];
__device__ float  g_buf2[BATCH*CCH*T2];
__device__ float  g_seq [BATCH*T2*HID];   // pair-interleaved: [pair][t][h][lane2]
__device__ float  g_hid [BATCH*NLAY*HID];

// ---------------- f32x2 helpers (b64 operands -> "l" constraint) ----------------
__device__ __forceinline__ u64 ffma2(u64 a, u64 b, u64 c) {
    u64 d;
    asm("fma.rn.f32x2 %0, %1, %2, %3;" : "=l"(d) : "l"(a), "l"(b), "l"(c));
    return d;
}
__device__ __forceinline__ u64 pack2(float x, float y) {
    u64 d;
    asm("mov.b64 %0, {%1, %2};" : "=l"(d) : "f"(x), "f"(y));
    return d;
}
__device__ __forceinline__ void unpack2(u64 d, float& x, float& y) {
    asm("mov.b64 {%0, %1}, %2;" : "=f"(x), "=f"(y) : "l"(d));
}

// ---------------- activation helpers ----------------
__device__ __forceinline__ float tanh_t(float x) {
    float y;
    asm("tanh.approx.f32 %0, %1;" : "=f"(y) : "f"(x));
    return y;
}
__device__ __forceinline__ float sigm_t(float x) {
    return fmaf(0.5f, tanh_t(0.5f * x), 0.5f);
}

// ---------------- K0: zero BN stat accumulators ----------------
__global__ void k_zero() {
    int t = threadIdx.x;
    if (t < CCH) { g_s1[t] = 0.0; g_q1[t] = 0.0; g_s2[t] = 0.0; g_q2[t] = 0.0; }
}

// ---------------- K1: conv1 + BN1 stats ----------------
__global__ void k_conv1(const float* __restrict__ x,
                        const float* __restrict__ w,
                        const float* __restrict__ bias) {
    int b = blockIdx.x;
    int tid = threadIdx.x;
    __shared__ float xs[CCH * TIN];
    __shared__ float ws[CCH * CCH * 5];
    __shared__ float bs[CCH];
    for (int i = tid; i < CCH * TIN; i += blockDim.x) xs[i] = x[b * CCH * TIN + i];
    if (tid < CCH * CCH * 5) ws[tid] = w[tid];
    if (tid < CCH) bs[tid] = bias[tid];
    __syncthreads();

    for (int c = 0; c < CCH; c++) {
        float s = 0.f, q = 0.f;
        for (int t = tid; t < T1; t += blockDim.x) {
            float a = bs[c];
            #pragma unroll
            for (int ci = 0; ci < CCH; ci++) {
                const float* xp = xs + ci * TIN + t;
                const float* wp = ws + (c * CCH + ci) * 5;
                #pragma unroll
                for (int k = 0; k < 5; k++) a = fmaf(xp[k], wp[k], a);
            }
            g_buf1[(b * CCH + c) * T1 + t] = a;
            s += a; q += a * a;
        }
        #pragma unroll
        for (int off = 16; off > 0; off >>= 1) {
            s += __shfl_down_sync(0xffffffffu, s, off);
            q += __shfl_down_sync(0xffffffffu, q, off);
        }
        if ((tid & 31) == 0) {
            atomicAdd(&g_s1[c], (double)s);
            atomicAdd(&g_q1[c], (double)q);
        }
    }
}

// ---------------- K2/K4: finalize BN scale/shift ----------------
__global__ void k_bnfin(const float* __restrict__ gam,
                        const float* __restrict__ bet, int which) {
    int c = threadIdx.x;
    if (c < CCH) {
        double* S = which ? g_s2 : g_s1;
        double* Q = which ? g_q2 : g_q1;
        float* out = which ? g_bn2 : g_bn1;
        double n = which ? ((double)BATCH * T2) : ((double)BATCH * T1);
        double m = S[c] / n;
        double v = Q[c] / n - m * m;
        float sc = gam[c] * rsqrtf((float)v + 1e-5f);
        out[c] = sc;
        out[CCH + c] = bet[c] - (float)m * sc;
    }
}

// ---------------- K3: BN1+relu -> conv2 + BN2 stats ----------------
__global__ void k_conv2(const float* __restrict__ w,
                        const float* __restrict__ bias) {
    int b = blockIdx.x;
    int tid = threadIdx.x;
    __shared__ float xs[CCH * T1];
    __shared__ float ws[CCH * CCH * 5];
    __shared__ float bs[CCH];
    for (int i = tid; i < CCH * T1; i += blockDim.x) {
        int ci = i / T1;
        float v = g_buf1[b * CCH * T1 + i];
        xs[i] = fmaxf(fmaf(v, g_bn1[ci], g_bn1[CCH + ci]), 0.f);
    }
    if (tid < CCH * CCH * 5) ws[tid] = w[tid];
    if (tid < CCH) bs[tid] = bias[tid];
    __syncthreads();

    for (int c = 0; c < CCH; c++) {
        float s = 0.f, q = 0.f;
        for (int t = tid; t < T2; t += blockDim.x) {
            float a = bs[c];
            #pragma unroll
            for (int ci = 0; ci < CCH; ci++) {
                const float* xp = xs + ci * T1 + t;
                const float* wp = ws + (c * CCH + ci) * 5;
                #pragma unroll
                for (int k = 0; k < 5; k++) a = fmaf(xp[k], wp[k], a);
            }
            g_buf2[(b * CCH + c) * T2 + t] = a;
            s += a; q += a * a;
        }
        #pragma unroll
        for (int off = 16; off > 0; off >>= 1) {
            s += __shfl_down_sync(0xffffffffu, s, off);
            q += __shfl_down_sync(0xffffffffu, q, off);
        }
        if ((tid & 31) == 0) {
            atomicAdd(&g_s2[c], (double)s);
            atomicAdd(&g_q2[c], (double)q);
        }
    }
}

// ---------------- K5: BN2+relu -> attn -> seq (batch-pair interleaved) ----------------
__global__ void k_attn(const float* __restrict__ aw,
                       const float* __restrict__ ab) {
    int b = blockIdx.x;
    int tid = threadIdx.x;
    __shared__ float xs[CCH * T2];
    __shared__ float ws[HID * CCH];
    __shared__ float bs[HID];
    for (int i = tid; i < CCH * T2; i += blockDim.x) {
        int ci = i / T2;
        float v = g_buf2[b * CCH * T2 + i];
        xs[i] = fmaxf(fmaf(v, g_bn2[ci], g_bn2[CCH + ci]), 0.f);
    }
    if (tid < HID * CCH) ws[tid] = aw[tid];
    if (tid < HID) bs[tid] = ab[tid];
    __syncthreads();

    size_t base = ((size_t)(b >> 1)) * T2 * HID * 2 + (b & 1);
    for (int idx = tid; idx < T2 * HID; idx += blockDim.x) {
        int t = idx / HID, h = idx % HID;
        float a = bs[h];
        #pragma unroll
        for (int c = 0; c < CCH; c++) a = fmaf(xs[c * T2 + t], ws[h * CCH + c], a);
        g_seq[base + (size_t)idx * 2] = fmaxf(a, 0.f);
    }
}

// ---------------- K6: 120-layer LSTM, 2 batches/block, 2 blocks/SM ----------------
// 256 blocks of 120 threads (GL=10 layers x 12 units). Two co-resident blocks
// per SM have INDEPENDENT barrier domains: while one block sits in its
// per-tick activation tail / barrier, the other issues FFMA2 on the same
// SMSPs, hiding the tick overhead under FMA-pipe time.
__global__ void __launch_bounds__(NTH, 2)
k_lstm(const float* __restrict__ Wih, const float* __restrict__ Whh,
       const float* __restrict__ bih, const float* __restrict__ bhh) {
    extern __shared__ __align__(16) u64 smem[];
    u64* seq_s  = smem;                    // [T2*HID] packed (b0,b1)
    u64* hbuf   = smem + SEQ_U;            // [2][GL][HID]
    u64* bias_s = smem + SEQ_U + HBUF_U;   // [NTH][4]

    int pair = blockIdx.x;
    int b0 = pair * 2, b1 = b0 + 1;
    int tid = threadIdx.x;
    int j = tid / HID;   // local layer in group
    int i = tid % HID;   // hidden unit

    // load this pair's interleaved sequence into shared (48 KB, float4)
    {
        const float4* src = (const float4*)(g_seq + (size_t)pair * T2 * HID * 2);
        float4* dst = (float4*)seq_s;
        for (int q = tid; q < (T2 * HID * 2) / 4; q += NTH) dst[q] = src[q];
    }

    for (int grp = 0; grp < NGRP; grp++) {
        int l = grp * GL + j;
        // zero h ring (h0 = c0 = 0)
        for (int q = tid; q < HBUF_U; q += NTH) hbuf[q] = 0ull;

        // pack this thread's 4 gate rows into duplicated-lane f32x2 registers
        u64 wih2[4][HID], whh2[4][HID];
        {
            const float* Wi = Wih + (size_t)l * 48 * HID;
            const float* Wh = Whh + (size_t)l * 48 * HID;
            #pragma unroll
            for (int r = 0; r < 4; r++) {
                int row = r * HID + i;
                #pragma unroll
                for (int m = 0; m < HID; m++) {
                    float wi = Wi[row * HID + m];
                    float wh = Wh[row * HID + m];
                    wih2[r][m] = pack2(wi, wi);
                    whh2[r][m] = pack2(wh, wh);
                }
                float bb = bih[l * 48 + row] + bhh[l * 48 + row];
                bias_s[tid * 4 + r] = pack2(bb, bb);
            }
        }
        float c0 = 0.f, c1 = 0.f;
        __syncthreads();

        for (int k = 0; k < T2 + GL - 1; k++) {
            int t = k - j;
            if ((unsigned)t < (unsigned)T2) {
                int p = k & 1;
                const u64* xp = (j == 0) ? (seq_s + t * HID)
                                         : (hbuf + ((p ^ 1) * GL + (j - 1)) * HID);
                const u64* hp = hbuf + ((p ^ 1) * GL + j) * HID;

                u64 a0 = bias_s[tid * 4 + 0], a1 = bias_s[tid * 4 + 1];
                u64 a2 = bias_s[tid * 4 + 2], a3 = bias_s[tid * 4 + 3];

                u64 v[HID];
                #pragma unroll
                for (int q = 0; q < HID / 2; q++) {
                    ulonglong2 tv = ((const ulonglong2*)xp)[q];
                    v[2 * q] = tv.x; v[2 * q + 1] = tv.y;
                }
                #pragma unroll
                for (int m = 0; m < HID; m++) {
                    u64 xm = v[m];
                    a0 = ffma2(wih2[0][m], xm, a0);
                    a1 = ffma2(wih2[1][m], xm, a1);
                    a2 = ffma2(wih2[2][m], xm, a2);
                    a3 = ffma2(wih2[3][m], xm, a3);
                }
                #pragma unroll
                for (int q = 0; q < HID / 2; q++) {
                    ulonglong2 tv = ((const ulonglong2*)hp)[q];
                    v[2 * q] = tv.x; v[2 * q + 1] = tv.y;
                }
                #pragma unroll
                for (int m = 0; m < HID; m++) {
                    u64 hm = v[m];
                    a0 = ffma2(whh2[0][m], hm, a0);
                    a1 = ffma2(whh2[1][m], hm, a1);
                    a2 = ffma2(whh2[2][m], hm, a2);
                    a3 = ffma2(whh2[3][m], hm, a3);
                }
                float g0x, g0y, g1x, g1y, g2x, g2y, g3x, g3y;
                unpack2(a0, g0x, g0y);
                unpack2(a1, g1x, g1y);
                unpack2(a2, g2x, g2y);
                unpack2(a3, g3x, g3y);
                // lane 0 (batch b0)
                float gi = sigm_t(g0x), gf = sigm_t(g1x), gg = tanh_t(g2x), go = sigm_t(g3x);
                c0 = gf * c0 + gi * gg;
                float h0 = go * tanh_t(c0);
                // lane 1 (batch b1)
                gi = sigm_t(g0y); gf = sigm_t(g1y); gg = tanh_t(g2y); go = sigm_t(g3y);
                c1 = gf * c1 + gi * gg;
                float h1 = go * tanh_t(c1);

                u64 hpk = pack2(h0, h1);
                hbuf[(p * GL + j) * HID + i] = hpk;
                if (j == GL - 1) seq_s[t * HID + i] = hpk;  // feeds next group
                if (t == T2 - 1) {
                    g_hid[((size_t)b0 * NLAY + l) * HID + i] = h0;
                    g_hid[((size_t)b1 * NLAY + l) * HID + i] = h1;
                }
            }
            __syncthreads();
        }
        __syncthreads();
    }
}

// ---------------- K7: MLP head -> (z, out, mu, log_var) ----------------
__global__ void k_head(const float* __restrict__ eps,
                       const float* __restrict__ l1w, const float* __restrict__ l1b,
                       const float* __restrict__ l2w, const float* __restrict__ l2b,
                       const float* __restrict__ muw, const float* __restrict__ mub,
                       const float* __restrict__ lvw, const float* __restrict__ lvb,
                       float* __restrict__ out) {
    __shared__ float W1[144], W2[144], WM[144], WV[144];
    __shared__ float B1[12], B2[12], BM[12], BV[12];
    int tid = threadIdx.x;
    for (int q = tid; q < 144; q += blockDim.x) {
        W1[q] = l1w[q]; W2[q] = l2w[q]; WM[q] = muw[q]; WV[q] = lvw[q];
    }
    if (tid < 12) { B1[tid] = l1b[tid]; B2[tid] = l2b[tid]; BM[tid] = mub[tid]; BV[tid] = lvb[tid]; }
    __syncthreads();

    int row = blockIdx.x * blockDim.x + tid;       // (b*120 + l)
    if (row >= BATCH * NLAY) return;
    const float* hp = g_hid + (size_t)row * HID;
    float h[HID], v1[HID], v2[HID];
    {
        float4 a = *(const float4*)(hp);
        float4 bq = *(const float4*)(hp + 4);
        float4 cq = *(const float4*)(hp + 8);
        h[0]=a.x; h[1]=a.y; h[2]=a.z; h[3]=a.w; h[4]=bq.x; h[5]=bq.y; h[6]=bq.z; h[7]=bq.w;
        h[8]=cq.x; h[9]=cq.y; h[10]=cq.z; h[11]=cq.w;
    }
    #pragma unroll
    for (int r = 0; r < HID; r++) {
        float a = B1[r];
        #pragma unroll
        for (int m = 0; m < HID; m++) a = fmaf(W1[r * HID + m], h[m], a);
        v1[r] = fmaxf(a, 0.f);
    }
    #pragma unroll
    for (int r = 0; r < HID; r++) {
        float a = B2[r];
        #pragma unroll
        for (int m = 0; m < HID; m++) a = fmaf(W2[r * HID + m], v1[m], a);
        v2[r] = fmaxf(a, 0.f);
    }
    #pragma unroll
    for (int r = 0; r < HID; r++) {
        float mu = BM[r], lv = BV[r];
        #pragma unroll
        for (int m = 0; m < HID; m++) {
            mu = fmaf(WM[r * HID + m], v2[m], mu);
            lv = fmaf(WV[r * HID + m], v2[m], lv);
        }
        float e = eps[(size_t)row * HID + r];
        float z = fmaf(__expf(0.5f * lv), e, mu);
        size_t idx = (size_t)row * HID + r;
        out[idx]              = z;
        out[NOUT + idx]       = v2[r];
        out[2 * (size_t)NOUT + idx] = mu;
        out[3 * (size_t)NOUT + idx] = lv;
    }
}

// ---------------- launcher ----------------
extern "C" void kernel_launch(void* const* d_in, const int* in_sizes, int n_in,
                              void* d_out, int out_size) {
    const float* x    = (const float*)d_in[0];
    const float* eps  = (const float*)d_in[1];
    const float* c1w  = (const float*)d_in[2];
    const float* c1b  = (const float*)d_in[3];
    const float* c2w  = (const float*)d_in[4];
    const float* c2b  = (const float*)d_in[5];
    const float* bn1g = (const float*)d_in[6];
    const float* bn1b = (const float*)d_in[7];
    const float* bn2g = (const float*)d_in[8];
    const float* bn2b = (const float*)d_in[9];
    const float* aw   = (const float*)d_in[10];
    const float* ab   = (const float*)d_in[11];
    const float* Wih  = (const float*)d_in[12];
    const float* Whh  = (const float*)d_in[13];
    const float* bih  = (const float*)d_in[14];
    const float* bhh  = (const float*)d_in[15];
    const float* l1w  = (const float*)d_in[16];
    const float* l1b  = (const float*)d_in[17];
    const float* l2w  = (const float*)d_in[18];
    const float* l2b  = (const float*)d_in[19];
    const float* muw  = (const float*)d_in[20];
    const float* mub  = (const float*)d_in[21];
    const float* lvw  = (const float*)d_in[22];
    const float* lvb  = (const float*)d_in[23];

    cudaFuncSetAttribute(k_lstm, cudaFuncAttributeMaxDynamicSharedMemorySize,
                         LSTM_SMEM_BYTES);

    k_zero<<<1, 32>>>();
    k_conv1<<<BATCH, 256>>>(x, c1w, c1b);
    k_bnfin<<<1, 32>>>(bn1g, bn1b, 0);
    k_conv2<<<BATCH, 256>>>(c2w, c2b);
    k_bnfin<<<1, 32>>>(bn2g, bn2b, 1);
    k_attn<<<BATCH, 256>>>(aw, ab);
    k_lstm<<<NPAIR, NTH, LSTM_SMEM_BYTES>>>(Wih, Whh, bih, bhh);
    k_head<<<(BATCH * NLAY) / 128, 128>>>(eps, l1w, l1b, l2w, l2b, muw, mub, lvw, lvb,
                                          (float*)d_out);
}